// round 12
// baseline (speedup 1.0000x reference)
#include <cuda_runtime.h>
#include <cuda_bf16.h>
#include <cstdint>
#include <cstddef>

#define B_   32
#define S_   2048
#define D_   256
#define G3_  768

// gi scratch: [dir][b][s][768]  (402 MB, fully rewritten every call)
__device__ float g_gi[(size_t)2 * B_ * S_ * G3_];

// ---------------------------------------------------------------------------
// helpers
// ---------------------------------------------------------------------------
__device__ __forceinline__ float2 unpack2(unsigned long long v) {
    float2 f;
    asm("mov.b64 {%0,%1}, %2;" : "=f"(f.x), "=f"(f.y) : "l"(v));
    return f;
}
__device__ __forceinline__ void ffma2(unsigned long long& d,
                                      unsigned long long a,
                                      unsigned long long b) {
    asm("fma.rn.f32x2 %0, %1, %2, %0;" : "+l"(d) : "l"(a), "l"(b));
}
__device__ __forceinline__ uint32_t smem_u32(const void* p) {
    uint32_t a;
    asm("{ .reg .u64 t; cvta.to.shared.u64 t, %1; cvt.u32.u64 %0, t; }"
        : "=r"(a) : "l"(p));
    return a;
}
__device__ __forceinline__ float fast_sig(float x) {
    return __fdividef(1.f, 1.f + __expf(-x));
}
__device__ __forceinline__ float fast_tanh(float x) {
    return __fdividef(2.f, 1.f + __expf(-2.f * x)) - 1.f;
}

// ---------------------------------------------------------------------------
// Kernel 1: gi[dir][m][n] = V[m][:] . W_ih(dir)[n][:] + b_ih[n]
// M = 65536, N = 768, K = 256. 128x128x8 fp32 SGEMM (proven).
// ---------------------------------------------------------------------------
__global__ __launch_bounds__(256, 2) void gi_gemm(
    const float* __restrict__ V,
    const float* __restrict__ Wf, const float* __restrict__ Wb,
    const float* __restrict__ bf, const float* __restrict__ bb)
{
    const int dir = blockIdx.z;
    const float* __restrict__ W   = dir ? Wb : Wf;
    const float* __restrict__ bih = dir ? bb : bf;
    const int m0 = blockIdx.x * 128;
    const int n0 = blockIdx.y * 128;

    __shared__ float As[2][8][132];
    __shared__ float Bs[2][8][132];

    const int tid = threadIdx.x;
    const int lr  = tid >> 1;
    const int lk  = (tid & 1) * 4;

    const float* aptr = V + (size_t)(m0 + lr) * 256 + lk;
    const float* bptr = W + (size_t)(n0 + lr) * 256 + lk;

    const int tx = tid & 15;
    const int ty = tid >> 4;

    float acc[8][8];
#pragma unroll
    for (int i = 0; i < 8; i++)
#pragma unroll
        for (int j = 0; j < 8; j++) acc[i][j] = 0.f;

    float4 a = *(const float4*)aptr;
    float4 b = *(const float4*)bptr;
    As[0][lk + 0][lr] = a.x; As[0][lk + 1][lr] = a.y;
    As[0][lk + 2][lr] = a.z; As[0][lk + 3][lr] = a.w;
    Bs[0][lk + 0][lr] = b.x; Bs[0][lk + 1][lr] = b.y;
    Bs[0][lk + 2][lr] = b.z; Bs[0][lk + 3][lr] = b.w;
    __syncthreads();

    int cur = 0;
    for (int kt = 0; kt < 32; kt++) {
        if (kt < 31) {
            a = *(const float4*)(aptr + (kt + 1) * 8);
            b = *(const float4*)(bptr + (kt + 1) * 8);
        }
#pragma unroll
        for (int k = 0; k < 8; k++) {
            float4 a0 = *(const float4*)&As[cur][k][ty * 8];
            float4 a1 = *(const float4*)&As[cur][k][ty * 8 + 4];
            float4 b0 = *(const float4*)&Bs[cur][k][tx * 8];
            float4 b1 = *(const float4*)&Bs[cur][k][tx * 8 + 4];
            float av[8] = {a0.x, a0.y, a0.z, a0.w, a1.x, a1.y, a1.z, a1.w};
            float bv[8] = {b0.x, b0.y, b0.z, b0.w, b1.x, b1.y, b1.z, b1.w};
#pragma unroll
            for (int i = 0; i < 8; i++)
#pragma unroll
                for (int j = 0; j < 8; j++)
                    acc[i][j] = fmaf(av[i], bv[j], acc[i][j]);
        }
        if (kt < 31) {
            const int nxt = cur ^ 1;
            As[nxt][lk + 0][lr] = a.x; As[nxt][lk + 1][lr] = a.y;
            As[nxt][lk + 2][lr] = a.z; As[nxt][lk + 3][lr] = a.w;
            Bs[nxt][lk + 0][lr] = b.x; Bs[nxt][lk + 1][lr] = b.y;
            Bs[nxt][lk + 2][lr] = b.z; Bs[nxt][lk + 3][lr] = b.w;
            __syncthreads();
            cur = nxt;
        }
    }

    float bias[8];
#pragma unroll
    for (int j = 0; j < 8; j++) bias[j] = bih[n0 + tx * 8 + j];

    float* gout = g_gi + (size_t)dir * B_ * S_ * G3_;
#pragma unroll
    for (int i = 0; i < 8; i++) {
        const size_t row = (size_t)(m0 + ty * 8 + i);
        float4 o0, o1;
        o0.x = acc[i][0] + bias[0]; o0.y = acc[i][1] + bias[1];
        o0.z = acc[i][2] + bias[2]; o0.w = acc[i][3] + bias[3];
        o1.x = acc[i][4] + bias[4]; o1.y = acc[i][5] + bias[5];
        o1.z = acc[i][6] + bias[6]; o1.w = acc[i][7] + bias[7];
        *(float4*)(gout + row * G3_ + n0 + tx * 8)     = o0;
        *(float4*)(gout + row * G3_ + n0 + tx * 8 + 4) = o1;
    }
}

// ---------------------------------------------------------------------------
// Kernel 2: GRU recurrence, two interleaved chains per cluster.
// Cluster of 4 CTAs = one (dir, batch-QUAD): chain A = batches (b0,b0+1),
// chain B = (b0+2,b0+3) — same direction => SAME weights, zero extra state.
// Schedule per step: waitA -> phaseA(compute/push/arrive) -> waitB ->
// phaseB(...). Each chain's DSMEM/barrier tail hides under the other
// chain's FMA phase. Terminal barrier.cluster (release) keeps every CTA
// alive until all final st.shared::cluster pushes have landed (the missing
// piece that crashed R10). grid = (4 ranks, 8 quads, 2 dirs) = 64 CTAs.
// Dyn SMEM (floats): wn[64*260] | hA[2][2][256] | hB[2][2][256] | 2 mbars
// ---------------------------------------------------------------------------
#define WN_STRIDE 260
#define SM_WN     0
#define SM_HA     (64 * WN_STRIDE)             // 16640
#define SM_HB     (SM_HA + 1024)               // 17664
#define SM_MBAR   (SM_HB + 1024)               // 18688  (byte off 74752, 8-aligned)
#define SM_FLOATS (SM_MBAR + 4)
#define SM_BYTES  (SM_FLOATS * 4)

#define MBAR_WAIT(mba, par)                                                   \
    asm volatile(                                                             \
        "{\n\t.reg .pred P;\n"                                                \
        "W%=:\n\t"                                                            \
        "mbarrier.try_wait.parity.acquire.cluster.shared::cta.b64 P, [%0], %1, 0x989680;\n\t" \
        "@!P bra W%=;\n\t}"                                                   \
        :: "r"(mba), "r"((uint32_t)(par)) : "memory")

__device__ __forceinline__ void gru_phase(
    float* hbuf, uint32_t hb, uint32_t mba,
    const unsigned long long (&wr2)[16], const unsigned long long (&wz2)[16],
    const float* wn_row,
    float br, float bz, float bn,
    const float* gi_my, const float* v_my, float* o_my,
    int step, int cl, int T, int ks, int bb, int j, int tid)
{
    const int p = step & 1;
    const float* hs = hbuf + p * 512;

    float g_r = 0.f, g_z = 0.f, g_n = 0.f, vv = 0.f, hp = 0.f;
    if (ks < 2) {
        g_r = gi_my[0];
        g_z = gi_my[256];
        g_n = gi_my[512];
        vv  = v_my[0];
        hp  = hs[bb * 256 + j];
    }

    unsigned long long ar0 = 0, az0 = 0, an0 = 0;
    unsigned long long ar1 = 0, az1 = 0, an1 = 0;
    const float* h0 = hs + ks * 32;
    const float* h1 = hs + 256 + ks * 32;
#pragma unroll
    for (int c = 0; c < 8; c++) {
        const int ci = (c ^ ks) & 7;
        ulonglong2 hv0 = *(const ulonglong2*)(h0 + 4 * ci);
        ulonglong2 hv1 = *(const ulonglong2*)(h1 + 4 * ci);
        ulonglong2 wn  = *(const ulonglong2*)(wn_row + 4 * ci);
        ffma2(ar0, wr2[2*c], hv0.x); ffma2(ar0, wr2[2*c+1], hv0.y);
        ffma2(az0, wz2[2*c], hv0.x); ffma2(az0, wz2[2*c+1], hv0.y);
        ffma2(an0, wn.x,     hv0.x); ffma2(an0, wn.y,       hv0.y);
        ffma2(ar1, wr2[2*c], hv1.x); ffma2(ar1, wr2[2*c+1], hv1.y);
        ffma2(az1, wz2[2*c], hv1.x); ffma2(az1, wz2[2*c+1], hv1.y);
        ffma2(an1, wn.x,     hv1.x); ffma2(an1, wn.y,       hv1.y);
    }

    float2 t;
    t = unpack2(ar0); float r0  = t.x + t.y;
    t = unpack2(az0); float z0  = t.x + t.y;
    t = unpack2(an0); float n0v = t.x + t.y;
    t = unpack2(ar1); float r1  = t.x + t.y;
    t = unpack2(az1); float z1  = t.x + t.y;
    t = unpack2(an1); float n1v = t.x + t.y;

    r0  += __shfl_xor_sync(0xffffffffu, r0, 1, 8);
    r0  += __shfl_xor_sync(0xffffffffu, r0, 2, 8);
    r0  += __shfl_xor_sync(0xffffffffu, r0, 4, 8);
    z0  += __shfl_xor_sync(0xffffffffu, z0, 1, 8);
    z0  += __shfl_xor_sync(0xffffffffu, z0, 2, 8);
    z0  += __shfl_xor_sync(0xffffffffu, z0, 4, 8);
    n0v += __shfl_xor_sync(0xffffffffu, n0v, 1, 8);
    n0v += __shfl_xor_sync(0xffffffffu, n0v, 2, 8);
    n0v += __shfl_xor_sync(0xffffffffu, n0v, 4, 8);
    r1  += __shfl_xor_sync(0xffffffffu, r1, 1, 8);
    r1  += __shfl_xor_sync(0xffffffffu, r1, 2, 8);
    r1  += __shfl_xor_sync(0xffffffffu, r1, 4, 8);
    z1  += __shfl_xor_sync(0xffffffffu, z1, 1, 8);
    z1  += __shfl_xor_sync(0xffffffffu, z1, 2, 8);
    z1  += __shfl_xor_sync(0xffffffffu, z1, 4, 8);
    n1v += __shfl_xor_sync(0xffffffffu, n1v, 1, 8);
    n1v += __shfl_xor_sync(0xffffffffu, n1v, 2, 8);
    n1v += __shfl_xor_sync(0xffffffffu, n1v, 4, 8);

    float hn = 0.f;
    if (ks < 2) {
        const float ar = bb ? r1  : r0;
        const float az = bb ? z1  : z0;
        const float an = bb ? n1v : n0v;

        const float r  = fast_sig(g_r + ar + br);
        const float z  = fast_sig(g_z + az + bz);
        const float n  = fast_tanh(g_n + r * (an + bn));
        hn = (1.f - z) * n + z * hp;

        const uint32_t la = hb + 4u * (uint32_t)(((p ^ 1) * 2 + bb) * 256 + j);
#pragma unroll
        for (int rdst = 0; rdst < 4; rdst++) {
            uint32_t ra;
            asm("mapa.shared::cluster.u32 %0, %1, %2;"
                : "=r"(ra) : "r"(la), "r"(rdst));
            asm volatile("st.shared::cluster.f32 [%0], %1;"
                         :: "r"(ra), "f"(hn) : "memory");
        }
    }

    __syncthreads();
    if (tid < 4) {
        uint32_t ra;
        asm("mapa.shared::cluster.u32 %0, %1, %2;"
            : "=r"(ra) : "r"(mba), "r"(tid));
        asm volatile("mbarrier.arrive.release.cluster.shared::cluster.b64 _, [%0];"
                     :: "r"(ra) : "memory");
    }

    if (ks < 2 && (unsigned)(step - cl) < (unsigned)T)
        o_my[(size_t)(step - cl) * 512] = hn + vv;
}

__global__ void __cluster_dims__(4, 1, 1) __launch_bounds__(512, 1)
rnn_rec(const float* __restrict__ whhf, const float* __restrict__ whhb,
        const float* __restrict__ bhhf, const float* __restrict__ bhhb,
        const float* __restrict__ V, float* __restrict__ out,
        int cl, int T)
{
    extern __shared__ __align__(16) float smem[];
    float* wn_s  = smem + SM_WN;
    float* hbufA = smem + SM_HA;
    float* hbufB = smem + SM_HB;

    const int tid = threadIdx.x;
    const int jl  = tid >> 3;
    const int ks  = tid & 7;
    unsigned rank;
    asm("mov.u32 %0, %%cluster_ctarank;" : "=r"(rank));
    const int j   = (int)rank * 64 + jl;
    const int dir = blockIdx.z;
    const int b0  = blockIdx.y * 4;

    const float* __restrict__ WHH = dir ? whhb : whhf;
    const float* __restrict__ BHH = dir ? bhhb : bhhf;

    unsigned long long wr2[16], wz2[16];
    {
        const float* pr = WHH + (size_t)(      j) * 256 + ks * 32;
        const float* pz = WHH + (size_t)(256 + j) * 256 + ks * 32;
#pragma unroll
        for (int c = 0; c < 8; c++) {
            const int ci = (c ^ ks) & 7;
            ulonglong2 q;
            q = *(const ulonglong2*)(pr + ci * 4);
            wr2[2*c] = q.x; wr2[2*c+1] = q.y;
            q = *(const ulonglong2*)(pz + ci * 4);
            wz2[2*c] = q.x; wz2[2*c+1] = q.y;
        }
    }
    const float br = BHH[j], bz = BHH[256 + j], bn = BHH[512 + j];

    {
        const float* srcn = WHH + (size_t)(512 + (int)rank * 64) * 256;
        for (int idx = tid; idx < 64 * 64; idx += 512) {
            const int u  = idx >> 6;
            const int c4 = idx & 63;
            *(float4*)(wn_s + u * WN_STRIDE + c4 * 4) =
                *(const float4*)(srcn + (size_t)u * 256 + c4 * 4);
        }
    }

    const uint32_t hbA = smem_u32(hbufA);
    const uint32_t hbB = smem_u32(hbufB);
    const uint32_t mbaA = smem_u32(smem + SM_MBAR);
    const uint32_t mbaB = mbaA + 8;

    // zero both h buffers (2048 floats = 512 float4) + init barriers
    ((float4*)hbufA)[tid] = make_float4(0.f, 0.f, 0.f, 0.f);
    if (tid == 0) {
        asm volatile("mbarrier.init.shared.b64 [%0], %1;" :: "r"(mbaA), "r"(4) : "memory");
        asm volatile("mbarrier.init.shared.b64 [%0], %1;" :: "r"(mbaB), "r"(4) : "memory");
    }
    __syncthreads();
    asm volatile("barrier.cluster.arrive.aligned;" ::: "memory");
    asm volatile("barrier.cluster.wait.aligned;"   ::: "memory");

    const int s0 = dir ? (S_ - 1) : 0;
    const ptrdiff_t gstep = dir ? -(ptrdiff_t)G3_ : (ptrdiff_t)G3_;
    const ptrdiff_t vstep = dir ? -(ptrdiff_t)256 : (ptrdiff_t)256;
    const int bb = ks & 1;

    const float* giA = g_gi + ((size_t)dir * B_ + b0 + bb) * S_ * G3_
                            + (size_t)s0 * G3_ + j;
    const float* vA  = V + ((size_t)(b0 + bb) * S_ + s0) * 256 + j;
    float* oA        = out + (size_t)(b0 + bb) * T * 512 + (size_t)dir * 256 + j;
    const float* giB = giA + (size_t)2 * S_ * G3_;
    const float* vB  = vA + (size_t)2 * S_ * 256;
    float* oB        = oA + (size_t)2 * T * 512;

    const float* wn_row = wn_s + jl * WN_STRIDE + ks * 32;

    for (int t = 0; t < S_; ++t) {
        const int pw = (t - 1) & 1;
        if (t) MBAR_WAIT(mbaA, pw);
        gru_phase(hbufA, hbA, mbaA, wr2, wz2, wn_row, br, bz, bn,
                  giA, vA, oA, t, cl, T, ks, bb, j, tid);
        giA += gstep; vA += vstep;

        if (t) MBAR_WAIT(mbaB, pw);
        gru_phase(hbufB, hbB, mbaB, wr2, wz2, wn_row, br, bz, bn,
                  giB, vB, oB, t, cl, T, ks, bb, j, tid);
        giB += gstep; vB += vstep;
    }

    // Terminal cluster sync: no CTA may exit while peers can still issue
    // st.shared::cluster into its SMEM (this omission crashed R10).
    asm volatile("barrier.cluster.arrive.aligned;" ::: "memory");
    asm volatile("barrier.cluster.wait.aligned;"   ::: "memory");
}

// ---------------------------------------------------------------------------
extern "C" void kernel_launch(void* const* d_in, const int* in_sizes, int n_in,
                              void* d_out, int out_size)
{
    const float* V    = (const float*)d_in[0];
    const float* wihf = (const float*)d_in[1];
    const float* whhf = (const float*)d_in[2];
    const float* bihf = (const float*)d_in[3];
    const float* bhhf = (const float*)d_in[4];
    const float* wihb = (const float*)d_in[5];
    const float* whhb = (const float*)d_in[6];
    const float* bihb = (const float*)d_in[7];
    const float* bhhb = (const float*)d_in[8];
    float* out = (float*)d_out;

    const int T  = out_size / (B_ * 512);   // 2028
    const int cl = (S_ - T) / 2;            // 10

    dim3 gg((B_ * S_) / 128, G3_ / 128, 2); // (512, 6, 2)
    gi_gemm<<<gg, 256>>>(V, wihf, wihb, bihf, bihb);

    cudaFuncSetAttribute(rnn_rec, cudaFuncAttributeMaxDynamicSharedMemorySize,
                         SM_BYTES);
    dim3 gr(4, B_ / 4, 2);                  // (4, 8, 2) — 64 CTAs, clusters of 4
    rnn_rec<<<gr, 512, SM_BYTES>>>(whhf, whhb, bhhf, bhhb, V, out, cl, T);
}

// round 13
// speedup vs baseline: 1.2709x; 1.2709x over previous
#include <cuda_runtime.h>
#include <cuda_bf16.h>
#include <cstdint>
#include <cstddef>

#define B_   32
#define S_   2048
#define D_   256
#define G3_  768

// gi scratch: [dir][b][s][768]  (402 MB, fully rewritten every call)
__device__ float g_gi[(size_t)2 * B_ * S_ * G3_];

// ---------------------------------------------------------------------------
// helpers
// ---------------------------------------------------------------------------
__device__ __forceinline__ float2 unpack2(unsigned long long v) {
    float2 f;
    asm("mov.b64 {%0,%1}, %2;" : "=f"(f.x), "=f"(f.y) : "l"(v));
    return f;
}
__device__ __forceinline__ void ffma2(unsigned long long& d,
                                      unsigned long long a,
                                      unsigned long long b) {
    asm("fma.rn.f32x2 %0, %1, %2, %0;" : "+l"(d) : "l"(a), "l"(b));
}
__device__ __forceinline__ uint32_t smem_u32(const void* p) {
    uint32_t a;
    asm("{ .reg .u64 t; cvta.to.shared.u64 t, %1; cvt.u32.u64 %0, t; }"
        : "=r"(a) : "l"(p));
    return a;
}
__device__ __forceinline__ float fast_sig(float x) {
    return __fdividef(1.f, 1.f + __expf(-x));
}
__device__ __forceinline__ float fast_tanh(float x) {
    return __fdividef(2.f, 1.f + __expf(-2.f * x)) - 1.f;
}

// ---------------------------------------------------------------------------
// Kernel 1: gi[dir][m][n] = V[m][:] . W_ih(dir)[n][:] + b_ih[n]
// M = 65536, N = 768, K = 256. 128x128x8 fp32 SGEMM (proven).
// ---------------------------------------------------------------------------
__global__ __launch_bounds__(256, 2) void gi_gemm(
    const float* __restrict__ V,
    const float* __restrict__ Wf, const float* __restrict__ Wb,
    const float* __restrict__ bf, const float* __restrict__ bb)
{
    const int dir = blockIdx.z;
    const float* __restrict__ W   = dir ? Wb : Wf;
    const float* __restrict__ bih = dir ? bb : bf;
    const int m0 = blockIdx.x * 128;
    const int n0 = blockIdx.y * 128;

    __shared__ float As[2][8][132];
    __shared__ float Bs[2][8][132];

    const int tid = threadIdx.x;
    const int lr  = tid >> 1;
    const int lk  = (tid & 1) * 4;

    const float* aptr = V + (size_t)(m0 + lr) * 256 + lk;
    const float* bptr = W + (size_t)(n0 + lr) * 256 + lk;

    const int tx = tid & 15;
    const int ty = tid >> 4;

    float acc[8][8];
#pragma unroll
    for (int i = 0; i < 8; i++)
#pragma unroll
        for (int j = 0; j < 8; j++) acc[i][j] = 0.f;

    float4 a = *(const float4*)aptr;
    float4 b = *(const float4*)bptr;
    As[0][lk + 0][lr] = a.x; As[0][lk + 1][lr] = a.y;
    As[0][lk + 2][lr] = a.z; As[0][lk + 3][lr] = a.w;
    Bs[0][lk + 0][lr] = b.x; Bs[0][lk + 1][lr] = b.y;
    Bs[0][lk + 2][lr] = b.z; Bs[0][lk + 3][lr] = b.w;
    __syncthreads();

    int cur = 0;
    for (int kt = 0; kt < 32; kt++) {
        if (kt < 31) {
            a = *(const float4*)(aptr + (kt + 1) * 8);
            b = *(const float4*)(bptr + (kt + 1) * 8);
        }
#pragma unroll
        for (int k = 0; k < 8; k++) {
            float4 a0 = *(const float4*)&As[cur][k][ty * 8];
            float4 a1 = *(const float4*)&As[cur][k][ty * 8 + 4];
            float4 b0 = *(const float4*)&Bs[cur][k][tx * 8];
            float4 b1 = *(const float4*)&Bs[cur][k][tx * 8 + 4];
            float av[8] = {a0.x, a0.y, a0.z, a0.w, a1.x, a1.y, a1.z, a1.w};
            float bv[8] = {b0.x, b0.y, b0.z, b0.w, b1.x, b1.y, b1.z, b1.w};
#pragma unroll
            for (int i = 0; i < 8; i++)
#pragma unroll
                for (int j = 0; j < 8; j++)
                    acc[i][j] = fmaf(av[i], bv[j], acc[i][j]);
        }
        if (kt < 31) {
            const int nxt = cur ^ 1;
            As[nxt][lk + 0][lr] = a.x; As[nxt][lk + 1][lr] = a.y;
            As[nxt][lk + 2][lr] = a.z; As[nxt][lk + 3][lr] = a.w;
            Bs[nxt][lk + 0][lr] = b.x; Bs[nxt][lk + 1][lr] = b.y;
            Bs[nxt][lk + 2][lr] = b.z; Bs[nxt][lk + 3][lr] = b.w;
            __syncthreads();
            cur = nxt;
        }
    }

    float bias[8];
#pragma unroll
    for (int j = 0; j < 8; j++) bias[j] = bih[n0 + tx * 8 + j];

    float* gout = g_gi + (size_t)dir * B_ * S_ * G3_;
#pragma unroll
    for (int i = 0; i < 8; i++) {
        const size_t row = (size_t)(m0 + ty * 8 + i);
        float4 o0, o1;
        o0.x = acc[i][0] + bias[0]; o0.y = acc[i][1] + bias[1];
        o0.z = acc[i][2] + bias[2]; o0.w = acc[i][3] + bias[3];
        o1.x = acc[i][4] + bias[4]; o1.y = acc[i][5] + bias[5];
        o1.z = acc[i][6] + bias[6]; o1.w = acc[i][7] + bias[7];
        *(float4*)(gout + row * G3_ + n0 + tx * 8)     = o0;
        *(float4*)(gout + row * G3_ + n0 + tx * 8 + 4) = o1;
    }
}

// ---------------------------------------------------------------------------
// Kernel 2: GRU recurrence. Cluster of 4 CTAs = one (dir, batch-pair).
// CTA rank owns hidden units [rank*64, rank*64+64). 512 threads:
//   jl = tid>>3 (unit), ks = tid&7 (32-wide K-slice)
//   w_r, w_z : registers (f32x2 pairs); w_n : SMEM (stride-260 rows)
// WARP-GRANULAR cluster sync (NEW): mbarrier count = 64 (16 warps x 4 CTAs).
// Each warp: __syncwarp -> lane0 arrive.release on all 4 CTAs' barriers ->
// independent parity wait. No per-step __syncthreads: warps decouple and
// their compute phases interleave across the step boundary.
// Dyn SMEM (floats): wn[64*260] | hbuf[2][2][256] | mbar
// grid = (4, 16, 2) = 128 CTAs x 512 thr.
// ---------------------------------------------------------------------------
#define WN_STRIDE 260
#define SM_WN     0
#define SM_HBUF   (64 * WN_STRIDE)             // 16640 floats
#define SM_MBAR   (SM_HBUF + 1024)             // 17664
#define SM_FLOATS (SM_MBAR + 4)
#define SM_BYTES  (SM_FLOATS * 4)

__global__ void __cluster_dims__(4, 1, 1) __launch_bounds__(512, 1)
rnn_rec(const float* __restrict__ whhf, const float* __restrict__ whhb,
        const float* __restrict__ bhhf, const float* __restrict__ bhhb,
        const float* __restrict__ V, float* __restrict__ out,
        int cl, int T)
{
    extern __shared__ __align__(16) float smem[];
    float* wn_s = smem + SM_WN;
    float* hbuf = smem + SM_HBUF;              // [phase][batch][256]

    const int tid = threadIdx.x;
    const int jl  = tid >> 3;          // 0..63 hidden unit within CTA slice
    const int ks  = tid & 7;           // 0..7  K-slice (32 wide)
    unsigned rank;
    asm("mov.u32 %0, %%cluster_ctarank;" : "=r"(rank));
    const int j   = (int)rank * 64 + jl;
    const int dir = blockIdx.z;
    const int b0  = blockIdx.y * 2;

    const float* __restrict__ WHH = dir ? whhb : whhf;
    const float* __restrict__ BHH = dir ? bhhb : bhhf;

    // w_r, w_z in registers as f32x2 pairs; 8 chunks of 4 floats,
    // chunk order XOR-swizzled by ks (conflict-free h reads).
    unsigned long long wr2[16], wz2[16];
    {
        const float* pr = WHH + (size_t)(      j) * 256 + ks * 32;
        const float* pz = WHH + (size_t)(256 + j) * 256 + ks * 32;
#pragma unroll
        for (int c = 0; c < 8; c++) {
            const int ci = (c ^ ks) & 7;
            ulonglong2 q;
            q = *(const ulonglong2*)(pr + ci * 4);
            wr2[2*c] = q.x; wr2[2*c+1] = q.y;
            q = *(const ulonglong2*)(pz + ci * 4);
            wz2[2*c] = q.x; wz2[2*c+1] = q.y;
        }
    }
    const float br = BHH[j], bz = BHH[256 + j], bn = BHH[512 + j];

    // w_n slice -> SMEM (coalesced float4), padded rows.
    {
        const float* srcn = WHH + (size_t)(512 + (int)rank * 64) * 256;
        for (int idx = tid; idx < 64 * 64; idx += 512) {
            const int u  = idx >> 6;
            const int c4 = idx & 63;
            *(float4*)(wn_s + u * WN_STRIDE + c4 * 4) =
                *(const float4*)(srcn + (size_t)u * 256 + c4 * 4);
        }
    }

    const uint32_t hb  = smem_u32(hbuf);
    const uint32_t mba = smem_u32(smem + SM_MBAR);

    if (tid < 256) ((float4*)hbuf)[tid] = make_float4(0.f, 0.f, 0.f, 0.f);
    if (tid == 0)
        asm volatile("mbarrier.init.shared.b64 [%0], %1;"
                     :: "r"(mba), "r"(64) : "memory");   // 16 warps x 4 CTAs
    __syncthreads();
    asm volatile("barrier.cluster.arrive.aligned;" ::: "memory");
    asm volatile("barrier.cluster.wait.aligned;"   ::: "memory");

    const int s0 = dir ? (S_ - 1) : 0;
    const ptrdiff_t gstep = dir ? -(ptrdiff_t)G3_ : (ptrdiff_t)G3_;
    const ptrdiff_t vstep = dir ? -(ptrdiff_t)256 : (ptrdiff_t)256;
    const int bb = ks & 1;   // gate-owner lanes ks<2: ks==0 -> batch0, ks==1 -> batch1

    const float* gi_my = g_gi + ((size_t)dir * B_ + b0 + bb) * S_ * G3_
                              + (size_t)s0 * G3_ + j;
    const float* v_my  = V + ((size_t)(b0 + bb) * S_ + s0) * 256 + j;
    float* o_my        = out + (size_t)(b0 + bb) * T * 512 + (size_t)dir * 256 + j;

    const float* wn_row = wn_s + jl * WN_STRIDE + ks * 32;

    float g_r = 0.f, g_z = 0.f, g_n = 0.f, vv = 0.f, hp = 0.f;

    for (int step = 0; step < S_; ++step) {
        const int p = step & 1;
        const float* hs = hbuf + p * 512;

        // early loads (gate-owner lanes ks<2) — hidden under the FMA phase
        if (ks < 2) {
            g_r = gi_my[0];
            g_z = gi_my[256];
            g_n = gi_my[512];
            vv  = v_my[0];
            hp  = hs[bb * 256 + j];
        }

        // --- gh partials: 2 batches x 3 gates x 32 K ---
        unsigned long long ar0 = 0, az0 = 0, an0 = 0;
        unsigned long long ar1 = 0, az1 = 0, an1 = 0;
        const float* h0 = hs + ks * 32;
        const float* h1 = hs + 256 + ks * 32;
#pragma unroll
        for (int c = 0; c < 8; c++) {
            const int ci = (c ^ ks) & 7;
            ulonglong2 hv0 = *(const ulonglong2*)(h0 + 4 * ci);
            ulonglong2 hv1 = *(const ulonglong2*)(h1 + 4 * ci);
            ulonglong2 wn  = *(const ulonglong2*)(wn_row + 4 * ci);
            ffma2(ar0, wr2[2*c], hv0.x); ffma2(ar0, wr2[2*c+1], hv0.y);
            ffma2(az0, wz2[2*c], hv0.x); ffma2(az0, wz2[2*c+1], hv0.y);
            ffma2(an0, wn.x,     hv0.x); ffma2(an0, wn.y,       hv0.y);
            ffma2(ar1, wr2[2*c], hv1.x); ffma2(ar1, wr2[2*c+1], hv1.y);
            ffma2(az1, wz2[2*c], hv1.x); ffma2(az1, wz2[2*c+1], hv1.y);
            ffma2(an1, wn.x,     hv1.x); ffma2(an1, wn.y,       hv1.y);
        }

        float2 t;
        t = unpack2(ar0); float r0  = t.x + t.y;
        t = unpack2(az0); float z0  = t.x + t.y;
        t = unpack2(an0); float n0v = t.x + t.y;
        t = unpack2(ar1); float r1  = t.x + t.y;
        t = unpack2(az1); float z1  = t.x + t.y;
        t = unpack2(an1); float n1v = t.x + t.y;

        // width-8 butterfly reduce
        r0  += __shfl_xor_sync(0xffffffffu, r0, 1, 8);
        r0  += __shfl_xor_sync(0xffffffffu, r0, 2, 8);
        r0  += __shfl_xor_sync(0xffffffffu, r0, 4, 8);
        z0  += __shfl_xor_sync(0xffffffffu, z0, 1, 8);
        z0  += __shfl_xor_sync(0xffffffffu, z0, 2, 8);
        z0  += __shfl_xor_sync(0xffffffffu, z0, 4, 8);
        n0v += __shfl_xor_sync(0xffffffffu, n0v, 1, 8);
        n0v += __shfl_xor_sync(0xffffffffu, n0v, 2, 8);
        n0v += __shfl_xor_sync(0xffffffffu, n0v, 4, 8);
        r1  += __shfl_xor_sync(0xffffffffu, r1, 1, 8);
        r1  += __shfl_xor_sync(0xffffffffu, r1, 2, 8);
        r1  += __shfl_xor_sync(0xffffffffu, r1, 4, 8);
        z1  += __shfl_xor_sync(0xffffffffu, z1, 1, 8);
        z1  += __shfl_xor_sync(0xffffffffu, z1, 2, 8);
        z1  += __shfl_xor_sync(0xffffffffu, z1, 4, 8);
        n1v += __shfl_xor_sync(0xffffffffu, n1v, 1, 8);
        n1v += __shfl_xor_sync(0xffffffffu, n1v, 2, 8);
        n1v += __shfl_xor_sync(0xffffffffu, n1v, 4, 8);

        float hn = 0.f;
        if (ks < 2) {
            const float ar = bb ? r1  : r0;
            const float az = bb ? z1  : z0;
            const float an = bb ? n1v : n0v;

            const float r  = fast_sig(g_r + ar + br);
            const float z  = fast_sig(g_z + az + bz);
            const float n  = fast_tanh(g_n + r * (an + bn));
            hn = (1.f - z) * n + z * hp;

            // replicate h' into every cluster CTA's next-phase buffer
            const uint32_t la = hb + 4u * (uint32_t)(((p ^ 1) * 2 + bb) * 256 + j);
#pragma unroll
            for (int rdst = 0; rdst < 4; rdst++) {
                uint32_t ra;
                asm("mapa.shared::cluster.u32 %0, %1, %2;"
                    : "=r"(ra) : "r"(la), "r"(rdst));
                asm volatile("st.shared::cluster.f32 [%0], %1;"
                             :: "r"(ra), "f"(hn) : "memory");
            }
        }

        // --- warp-granular cluster sync: no __syncthreads ---
        __syncwarp();
        if ((tid & 31) == 0) {
#pragma unroll
            for (int rdst = 0; rdst < 4; rdst++) {
                uint32_t ra;
                asm("mapa.shared::cluster.u32 %0, %1, %2;"
                    : "=r"(ra) : "r"(mba), "r"(rdst));
                asm volatile("mbarrier.arrive.release.cluster.shared::cluster.b64 _, [%0];"
                             :: "r"(ra) : "memory");
            }
        }

        // output store off the sync path
        if (ks < 2 && (unsigned)(step - cl) < (unsigned)T)
            o_my[(size_t)(step - cl) * 512] = hn + vv;

        gi_my += gstep;
        v_my  += vstep;

        {
            const uint32_t par = (uint32_t)(step & 1);
            asm volatile(
                "{\n\t"
                ".reg .pred P;\n"
                "W%=:\n\t"
                "mbarrier.try_wait.parity.acquire.cluster.shared::cta.b64 P, [%0], %1, 0x989680;\n\t"
                "@!P bra W%=;\n\t"
                "}"
                :: "r"(mba), "r"(par) : "memory");
        }
    }

    // Terminal cluster sync: no CTA may exit while peers can still issue
    // st.shared::cluster / arrives into its SMEM.
    asm volatile("barrier.cluster.arrive.aligned;" ::: "memory");
    asm volatile("barrier.cluster.wait.aligned;"   ::: "memory");
}

// ---------------------------------------------------------------------------
extern "C" void kernel_launch(void* const* d_in, const int* in_sizes, int n_in,
                              void* d_out, int out_size)
{
    const float* V    = (const float*)d_in[0];
    const float* wihf = (const float*)d_in[1];
    const float* whhf = (const float*)d_in[2];
    const float* bihf = (const float*)d_in[3];
    const float* bhhf = (const float*)d_in[4];
    const float* wihb = (const float*)d_in[5];
    const float* whhb = (const float*)d_in[6];
    const float* bihb = (const float*)d_in[7];
    const float* bhhb = (const float*)d_in[8];
    float* out = (float*)d_out;

    const int T  = out_size / (B_ * 512);   // 2028
    const int cl = (S_ - T) / 2;            // 10

    dim3 gg((B_ * S_) / 128, G3_ / 128, 2); // (512, 6, 2)
    gi_gemm<<<gg, 256>>>(V, wihf, wihb, bihf, bihb);

    cudaFuncSetAttribute(rnn_rec, cudaFuncAttributeMaxDynamicSharedMemorySize,
                         SM_BYTES);
    dim3 gr(4, B_ / 2, 2);                  // (4, 16, 2) — clusters of 4
    rnn_rec<<<gr, 512, SM_BYTES>>>(whhf, whhb, bhhf, bhhb, V, out, cl, T);
}

// round 15
// speedup vs baseline: 1.9901x; 1.5659x over previous
#include <cuda_runtime.h>
#include <cuda_bf16.h>
#include <cstdint>
#include <cstddef>

#define B_   32
#define S_   2048
#define D_   256
#define G3_  768

// scratch: gi [dir][b][s][768], split-bf16 copies of v and w_ih
__device__ float          g_gi[(size_t)2 * B_ * S_ * G3_];
__device__ __nv_bfloat16  g_vh[(size_t)B_ * S_ * D_];
__device__ __nv_bfloat16  g_vl[(size_t)B_ * S_ * D_];
__device__ __nv_bfloat16  g_wh[(size_t)2 * G3_ * D_];
__device__ __nv_bfloat16  g_wl[(size_t)2 * G3_ * D_];

// ---------------------------------------------------------------------------
// helpers
// ---------------------------------------------------------------------------
__device__ __forceinline__ float2 unpack2(unsigned long long v) {
    float2 f;
    asm("mov.b64 {%0,%1}, %2;" : "=f"(f.x), "=f"(f.y) : "l"(v));
    return f;
}
__device__ __forceinline__ void ffma2(unsigned long long& d,
                                      unsigned long long a,
                                      unsigned long long b) {
    asm("fma.rn.f32x2 %0, %1, %2, %0;" : "+l"(d) : "l"(a), "l"(b));
}
__device__ __forceinline__ uint32_t smem_u32(const void* p) {
    uint32_t a;
    asm("{ .reg .u64 t; cvta.to.shared.u64 t, %1; cvt.u32.u64 %0, t; }"
        : "=r"(a) : "l"(p));
    return a;
}
__device__ __forceinline__ float fast_sig(float x) {
    return __fdividef(1.f, 1.f + __expf(-x));
}
__device__ __forceinline__ float fast_tanh(float x) {
    return __fdividef(2.f, 1.f + __expf(-2.f * x)) - 1.f;
}

#define LDSM4(r, a)                                                           \
    asm volatile("ldmatrix.sync.aligned.m8n8.x4.shared.b16 {%0,%1,%2,%3}, [%4];" \
                 : "=r"((r)[0]), "=r"((r)[1]), "=r"((r)[2]), "=r"((r)[3])     \
                 : "r"(a))

#define MMA16816(d, a, b)                                                     \
    asm volatile("mma.sync.aligned.m16n8k16.row.col.f32.bf16.bf16.f32 "       \
                 "{%0,%1,%2,%3}, {%4,%5,%6,%7}, {%8,%9}, {%0,%1,%2,%3};"      \
                 : "+f"((d)[0]), "+f"((d)[1]), "+f"((d)[2]), "+f"((d)[3])     \
                 : "r"((a)[0]), "r"((a)[1]), "r"((a)[2]), "r"((a)[3]),        \
                   "r"((b)[0]), "r"((b)[1]))

// ---------------------------------------------------------------------------
// Kernel 0: split fp32 -> bf16 hi + bf16 lo (residual)
// ---------------------------------------------------------------------------
__global__ void cvt_split(const float* __restrict__ src,
                          __nv_bfloat16* __restrict__ dh,
                          __nv_bfloat16* __restrict__ dl, int n4)
{
    int i = blockIdx.x * blockDim.x + threadIdx.x;
    if (i >= n4) return;
    float4 x = *(const float4*)(src + (size_t)i * 4);
    __nv_bfloat16 h0 = __float2bfloat16(x.x), h1 = __float2bfloat16(x.y);
    __nv_bfloat16 h2 = __float2bfloat16(x.z), h3 = __float2bfloat16(x.w);
    __nv_bfloat16 l0 = __float2bfloat16(x.x - __bfloat162float(h0));
    __nv_bfloat16 l1 = __float2bfloat16(x.y - __bfloat162float(h1));
    __nv_bfloat16 l2 = __float2bfloat16(x.z - __bfloat162float(h2));
    __nv_bfloat16 l3 = __float2bfloat16(x.w - __bfloat162float(h3));
    __nv_bfloat162* ph = (__nv_bfloat162*)(dh + (size_t)i * 4);
    __nv_bfloat162* pl = (__nv_bfloat162*)(dl + (size_t)i * 4);
    ph[0] = __nv_bfloat162(h0, h1); ph[1] = __nv_bfloat162(h2, h3);
    pl[0] = __nv_bfloat162(l0, l1); pl[1] = __nv_bfloat162(l2, l3);
}

// ---------------------------------------------------------------------------
// Kernel 1: gi via mma.sync (HMMA) split-bf16.
// gi[m][n] = sum_k v[m][k] w[n][k] + b[n]  ~= Ah·Bh + Ah·Bl + Al·Bh (f32 acc).
// CTA 128x128 tile, 256 thr (8 warps x m16). K in 4 chunks of 64, SMEM rows
// padded to 144 B (ldmatrix conflict-free). NT fragments: A no-trans x4,
// B [n][k] no-trans x4 = 2 n-tiles. grid = (512 m-tiles, 6 n-tiles, 2 dirs).
// SMEM bytes: Ah[128*144] | Al | Bh | Bl  = 73728.
// ---------------------------------------------------------------------------
#define GM_AH 0
#define GM_AL 18432
#define GM_BH 36864
#define GM_BL 55296
#define GM_BYTES 73728

__global__ __launch_bounds__(256) void gi_mma(
    const float* __restrict__ bf, const float* __restrict__ bb)
{
    extern __shared__ __align__(16) char ms[];
    const int tid  = threadIdx.x;
    const int wid  = tid >> 5;
    const int lane = tid & 31;
    const int mbase = blockIdx.x * 128;
    const int nbase = blockIdx.y * 128;
    const int dir   = blockIdx.z;
    const uint32_t sb = smem_u32(ms);

    const __nv_bfloat16* srcs[4] = {
        g_vh + (size_t)mbase * 256,
        g_vl + (size_t)mbase * 256,
        g_wh + ((size_t)dir * G3_ + nbase) * 256,
        g_wl + ((size_t)dir * G3_ + nbase) * 256
    };

    float acc[16][4];
#pragma unroll
    for (int t = 0; t < 16; t++)
#pragma unroll
        for (int q = 0; q < 4; q++) acc[t][q] = 0.f;

    // fragment addresses (constant across chunks, vary by k16)
    const uint32_t a_row  = (uint32_t)(wid * 16 + (lane & 15));
    const uint32_t a_base = sb + GM_AH + a_row * 144 + ((lane >> 4) * 16);
    const uint32_t b_row  = (uint32_t)((lane & 7) + ((lane >> 4) & 1) * 8);
    const uint32_t b_koff = (uint32_t)(((lane >> 3) & 1) * 16);

    for (int ch = 0; ch < 4; ++ch) {
        // ---- load chunk: 4 matrices x 128 rows x 64 bf16 (uint4 coalesced)
#pragma unroll
        for (int it = 0; it < 16; ++it) {
            const int idx = tid + it * 256;
            const int m   = it >> 2;          // compile-time matrix select
            const int r   = (idx >> 3) & 127;
            const int c   = idx & 7;
            *(uint4*)(ms + m * 18432 + r * 144 + c * 16) =
                *(const uint4*)(srcs[m] + (size_t)r * 256 + ch * 64 + c * 8);
        }
        __syncthreads();

#pragma unroll
        for (int k16 = 0; k16 < 4; ++k16) {
            uint32_t ah[4], al[4];
            const uint32_t aa = a_base + k16 * 32;
            LDSM4(ah, aa);
            LDSM4(al, aa + (GM_AL - GM_AH));

#pragma unroll
            for (int np = 0; np < 8; ++np) {
                const uint32_t ba = sb + GM_BH + (np * 16 + b_row) * 144
                                    + b_koff + k16 * 32;
                uint32_t bh[4], bl[4];
                LDSM4(bh, ba);
                MMA16816(acc[2*np],   ah, (bh + 0));
                MMA16816(acc[2*np+1], ah, (bh + 2));
                MMA16816(acc[2*np],   al, (bh + 0));
                MMA16816(acc[2*np+1], al, (bh + 2));
                LDSM4(bl, ba + (GM_BL - GM_BH));
                MMA16816(acc[2*np],   ah, (bl + 0));
                MMA16816(acc[2*np+1], ah, (bl + 2));
            }
        }
        __syncthreads();
    }

    // ---- epilogue: D fragment (row = group, cols = thread*2) + bias
    const float* bih = dir ? bb : bf;
    float* gout = g_gi + ((size_t)dir * B_ * S_ + mbase) * G3_ + nbase;
    const int r0 = wid * 16 + (lane >> 2);
    const int cb = (lane & 3) * 2;
#pragma unroll
    for (int t = 0; t < 16; ++t) {
        const int col = t * 8 + cb;
        const float b0v = bih[nbase + col];
        const float b1v = bih[nbase + col + 1];
        float2 o0, o1;
        o0.x = acc[t][0] + b0v; o0.y = acc[t][1] + b1v;
        o1.x = acc[t][2] + b0v; o1.y = acc[t][3] + b1v;
        *(float2*)(gout + (size_t)r0 * G3_ + col)       = o0;
        *(float2*)(gout + (size_t)(r0 + 8) * G3_ + col) = o1;
    }
}

// ---------------------------------------------------------------------------
// Kernel 2: GRU recurrence — EXACT proven-best config (bench 4293, rec 3.15ms).
// Cluster of 4 CTAs = one (dir, batch-pair); 256 thr; jl=tid>>2, ks=tid&3;
// w_r,w_z register f32x2 pairs; w_n SMEM (stride-260); per-step
// __syncthreads + 4x mbarrier arrive.release.cluster + parity wait.
// ---------------------------------------------------------------------------
#define WN_STRIDE 260
#define SM_WN     0
#define SM_HBUF   (64 * WN_STRIDE)
#define SM_MBAR   (SM_HBUF + 1024)
#define SM_FLOATS (SM_MBAR + 4)
#define SM_BYTES  (SM_FLOATS * 4)

__global__ void __cluster_dims__(4, 1, 1) __launch_bounds__(256, 1)
rnn_rec(const float* __restrict__ whhf, const float* __restrict__ whhb,
        const float* __restrict__ bhhf, const float* __restrict__ bhhb,
        const float* __restrict__ V, float* __restrict__ out,
        int cl, int T)
{
    extern __shared__ __align__(16) float smem[];
    float* wn_s = smem + SM_WN;
    float* hbuf = smem + SM_HBUF;

    const int tid = threadIdx.x;
    const int jl  = tid >> 2;
    const int ks  = tid & 3;
    unsigned rank;
    asm("mov.u32 %0, %%cluster_ctarank;" : "=r"(rank));
    const int j   = (int)rank * 64 + jl;
    const int dir = blockIdx.z;
    const int b0  = blockIdx.y * 2;

    const float* __restrict__ WHH = dir ? whhb : whhf;
    const float* __restrict__ BHH = dir ? bhhb : bhhf;

    unsigned long long wr2[32], wz2[32];
    {
        const float* pr = WHH + (size_t)(      j) * 256 + ks * 64;
        const float* pz = WHH + (size_t)(256 + j) * 256 + ks * 64;
#pragma unroll
        for (int i = 0; i < 16; i++) {
            const int ci = (i ^ (ks << 1)) & 15;
            ulonglong2 q;
            q = *(const ulonglong2*)(pr + ci * 4);
            wr2[2*i] = q.x; wr2[2*i+1] = q.y;
            q = *(const ulonglong2*)(pz + ci * 4);
            wz2[2*i] = q.x; wz2[2*i+1] = q.y;
        }
    }
    const float br = BHH[j], bz = BHH[256 + j], bn = BHH[512 + j];

    {
        const float* srcn = WHH + (size_t)(512 + (int)rank * 64) * 256;
        for (int idx = tid; idx < 64 * 64; idx += 256) {
            const int u  = idx >> 6;
            const int c4 = idx & 63;
            *(float4*)(wn_s + u * WN_STRIDE + c4 * 4) =
                *(const float4*)(srcn + (size_t)u * 256 + c4 * 4);
        }
    }

    const uint32_t hb  = smem_u32(hbuf);
    const uint32_t mba = smem_u32(smem + SM_MBAR);

    if (tid < 128) ((float4*)hbuf)[tid] = make_float4(0.f, 0.f, 0.f, 0.f);
    if (tid == 0)
        asm volatile("mbarrier.init.shared.b64 [%0], %1;"
                     :: "r"(mba), "r"(4) : "memory");
    __syncthreads();
    asm volatile("barrier.cluster.arrive.aligned;" ::: "memory");
    asm volatile("barrier.cluster.wait.aligned;"   ::: "memory");

    const int s0 = dir ? (S_ - 1) : 0;
    const ptrdiff_t gstep = dir ? -(ptrdiff_t)G3_ : (ptrdiff_t)G3_;
    const ptrdiff_t vstep = dir ? -(ptrdiff_t)256 : (ptrdiff_t)256;
    const int bb = ks & 1;

    const float* gi_my = g_gi + ((size_t)dir * B_ + b0 + bb) * S_ * G3_
                              + (size_t)s0 * G3_ + j;
    const float* v_my  = V + ((size_t)(b0 + bb) * S_ + s0) * 256 + j;
    float* o_my        = out + (size_t)(b0 + bb) * T * 512 + (size_t)dir * 256 + j;

    const float* wn_row = wn_s + jl * WN_STRIDE + ks * 64;

    float g_r = 0.f, g_z = 0.f, g_n = 0.f, vv = 0.f, hp = 0.f;

    for (int step = 0; step < S_; ++step) {
        const int p = step & 1;
        const float* hs = hbuf + p * 512;

        if (ks < 2) {
            g_r = gi_my[0];
            g_z = gi_my[256];
            g_n = gi_my[512];
            vv  = v_my[0];
            hp  = hs[bb * 256 + j];
        }

        unsigned long long ar0 = 0, az0 = 0, an0 = 0;
        unsigned long long ar1 = 0, az1 = 0, an1 = 0;
        const float* h0 = hs + ks * 64;
        const float* h1 = hs + 256 + ks * 64;
#pragma unroll
        for (int i = 0; i < 16; i++) {
            const int ci = (i ^ (ks << 1)) & 15;
            ulonglong2 hv0 = *(const ulonglong2*)(h0 + 4 * ci);
            ulonglong2 hv1 = *(const ulonglong2*)(h1 + 4 * ci);
            ulonglong2 wn  = *(const ulonglong2*)(wn_row + 4 * ci);
            ffma2(ar0, wr2[2*i], hv0.x); ffma2(ar0, wr2[2*i+1], hv0.y);
            ffma2(az0, wz2[2*i], hv0.x); ffma2(az0, wz2[2*i+1], hv0.y);
            ffma2(an0, wn.x,     hv0.x); ffma2(an0, wn.y,       hv0.y);
            ffma2(ar1, wr2[2*i], hv1.x); ffma2(ar1, wr2[2*i+1], hv1.y);
            ffma2(az1, wz2[2*i], hv1.x); ffma2(az1, wz2[2*i+1], hv1.y);
            ffma2(an1, wn.x,     hv1.x); ffma2(an1, wn.y,       hv1.y);
        }

        float2 t;
        t = unpack2(ar0); float r0  = t.x + t.y;
        t = unpack2(az0); float z0  = t.x + t.y;
        t = unpack2(an0); float n0v = t.x + t.y;
        t = unpack2(ar1); float r1  = t.x + t.y;
        t = unpack2(az1); float z1  = t.x + t.y;
        t = unpack2(an1); float n1v = t.x + t.y;

        r0  += __shfl_xor_sync(0xffffffffu, r0, 1, 4);
        r0  += __shfl_xor_sync(0xffffffffu, r0, 2, 4);
        z0  += __shfl_xor_sync(0xffffffffu, z0, 1, 4);
        z0  += __shfl_xor_sync(0xffffffffu, z0, 2, 4);
        n0v += __shfl_xor_sync(0xffffffffu, n0v, 1, 4);
        n0v += __shfl_xor_sync(0xffffffffu, n0v, 2, 4);
        r1  += __shfl_xor_sync(0xffffffffu, r1, 1, 4);
        r1  += __shfl_xor_sync(0xffffffffu, r1, 2, 4);
        z1  += __shfl_xor_sync(0xffffffffu, z1, 1, 4);
        z1  += __shfl_xor_sync(0xffffffffu, z1, 2, 4);
        n1v += __shfl_xor_sync(0xffffffffu, n1v, 1, 4);
        n1v += __shfl_xor_sync(0xffffffffu, n1v, 2, 4);

        if (ks < 2) {
            const float ar = bb ? r1  : r0;
            const float az = bb ? z1  : z0;
            const float an = bb ? n1v : n0v;

            const float r  = fast_sig(g_r + ar + br);
            const float z  = fast_sig(g_z + az + bz);
            const float n  = fast_tanh(g_n + r * (an + bn));
            const float hn = (1.f - z) * n + z * hp;

            const uint32_t la = hb + 4u * (uint32_t)(((p ^ 1) * 2 + bb) * 256 + j);
#pragma unroll
            for (int rdst = 0; rdst < 4; rdst++) {
                uint32_t ra;
                asm("mapa.shared::cluster.u32 %0, %1, %2;"
                    : "=r"(ra) : "r"(la), "r"(rdst));
                asm volatile("st.shared::cluster.f32 [%0], %1;"
                             :: "r"(ra), "f"(hn) : "memory");
            }

            if ((unsigned)(step - cl) < (unsigned)T)
                o_my[(size_t)(step - cl) * 512] = hn + vv;
        }

        gi_my += gstep;
        v_my  += vstep;

        __syncthreads();
        if (tid < 4) {
            uint32_t ra;
            asm("mapa.shared::cluster.u32 %0, %1, %2;"
                : "=r"(ra) : "r"(mba), "r"(tid));
            asm volatile("mbarrier.arrive.release.cluster.shared::cluster.b64 _, [%0];"
                         :: "r"(ra) : "memory");
        }
        {
            const uint32_t par = (uint32_t)(step & 1);
            asm volatile(
                "{\n\t"
                ".reg .pred P;\n"
                "W%=:\n\t"
                "mbarrier.try_wait.parity.acquire.cluster.shared::cta.b64 P, [%0], %1, 0x989680;\n\t"
                "@!P bra W%=;\n\t"
                "}"
                :: "r"(mba), "r"(par) : "memory");
        }
    }
}

// ---------------------------------------------------------------------------
extern "C" void kernel_launch(void* const* d_in, const int* in_sizes, int n_in,
                              void* d_out, int out_size)
{
    const float* V    = (const float*)d_in[0];
    const float* wihf = (const float*)d_in[1];
    const float* whhf = (const float*)d_in[2];
    const float* bihf = (const float*)d_in[3];
    const float* bhhf = (const float*)d_in[4];
    const float* wihb = (const float*)d_in[5];
    const float* whhb = (const float*)d_in[6];
    const float* bihb = (const float*)d_in[7];
    const float* bhhb = (const float*)d_in[8];
    float* out = (float*)d_out;

    const int T  = out_size / (B_ * 512);   // 2028
    const int cl = (S_ - T) / 2;            // 10

    __nv_bfloat16 *vh, *vl, *wh, *wl;
    cudaGetSymbolAddress((void**)&vh, g_vh);
    cudaGetSymbolAddress((void**)&vl, g_vl);
    cudaGetSymbolAddress((void**)&wh, g_wh);
    cudaGetSymbolAddress((void**)&wl, g_wl);

    // split fp32 -> bf16 hi/lo
    cvt_split<<<(B_ * S_ * D_) / 1024, 256>>>(V, vh, vl, (B_ * S_ * D_) / 4);
    cvt_split<<<(G3_ * D_) / 1024, 256>>>(wihf, wh, wl, (G3_ * D_) / 4);
    cvt_split<<<(G3_ * D_) / 1024, 256>>>(wihb, wh + (size_t)G3_ * D_,
                                          wl + (size_t)G3_ * D_, (G3_ * D_) / 4);

    // tensor-core (HMMA) gi GEMM
    cudaFuncSetAttribute(gi_mma, cudaFuncAttributeMaxDynamicSharedMemorySize,
                         GM_BYTES);
    gi_mma<<<dim3((B_ * S_) / 128, G3_ / 128, 2), 256, GM_BYTES>>>(bihf, bihb);

    // recurrence (proven-best config)
    cudaFuncSetAttribute(rnn_rec, cudaFuncAttributeMaxDynamicSharedMemorySize,
                         SM_BYTES);
    rnn_rec<<<dim3(4, B_ / 2, 2), 256, SM_BYTES>>>(whhf, whhb, bhhf, bhhb,
                                                   V, out, cl, T);
}

// round 16
// speedup vs baseline: 2.0700x; 1.0401x over previous
#include <cuda_runtime.h>
#include <cuda_bf16.h>
#include <cstdint>
#include <cstddef>

#define B_   32
#define S_   2048
#define D_   256
#define G3_  768

// scratch: gi [dir][b][s][768], split-bf16 copies of v and w_ih
__device__ float          g_gi[(size_t)2 * B_ * S_ * G3_];
__device__ __nv_bfloat16  g_vh[(size_t)B_ * S_ * D_];
__device__ __nv_bfloat16  g_vl[(size_t)B_ * S_ * D_];
__device__ __nv_bfloat16  g_wh[(size_t)2 * G3_ * D_];
__device__ __nv_bfloat16  g_wl[(size_t)2 * G3_ * D_];

// ---------------------------------------------------------------------------
// helpers
// ---------------------------------------------------------------------------
__device__ __forceinline__ float2 unpack2(unsigned long long v) {
    float2 f;
    asm("mov.b64 {%0,%1}, %2;" : "=f"(f.x), "=f"(f.y) : "l"(v));
    return f;
}
__device__ __forceinline__ void ffma2(unsigned long long& d,
                                      unsigned long long a,
                                      unsigned long long b) {
    asm("fma.rn.f32x2 %0, %1, %2, %0;" : "+l"(d) : "l"(a), "l"(b));
}
__device__ __forceinline__ uint32_t smem_u32(const void* p) {
    uint32_t a;
    asm("{ .reg .u64 t; cvta.to.shared.u64 t, %1; cvt.u32.u64 %0, t; }"
        : "=r"(a) : "l"(p));
    return a;
}
__device__ __forceinline__ float fast_sig(float x) {
    return __fdividef(1.f, 1.f + __expf(-x));
}
__device__ __forceinline__ float fast_tanh(float x) {
    return __fdividef(2.f, 1.f + __expf(-2.f * x)) - 1.f;
}
__device__ __forceinline__ void cp16(uint32_t s, const void* g) {
    asm volatile("cp.async.cg.shared.global [%0], [%1], 16;"
                 :: "r"(s), "l"(g) : "memory");
}
#define CP_COMMIT() asm volatile("cp.async.commit_group;" ::: "memory")
#define CP_WAIT(n)  asm volatile("cp.async.wait_group %0;" :: "n"(n) : "memory")

#define LDSM4(r, a)                                                           \
    asm volatile("ldmatrix.sync.aligned.m8n8.x4.shared.b16 {%0,%1,%2,%3}, [%4];" \
                 : "=r"((r)[0]), "=r"((r)[1]), "=r"((r)[2]), "=r"((r)[3])     \
                 : "r"(a))

#define MMA16816(d, a, b)                                                     \
    asm volatile("mma.sync.aligned.m16n8k16.row.col.f32.bf16.bf16.f32 "       \
                 "{%0,%1,%2,%3}, {%4,%5,%6,%7}, {%8,%9}, {%0,%1,%2,%3};"      \
                 : "+f"((d)[0]), "+f"((d)[1]), "+f"((d)[2]), "+f"((d)[3])     \
                 : "r"((a)[0]), "r"((a)[1]), "r"((a)[2]), "r"((a)[3]),        \
                   "r"((b)[0]), "r"((b)[1]))

// ---------------------------------------------------------------------------
// Kernel 0: split fp32 -> bf16 hi + bf16 lo (residual)
// ---------------------------------------------------------------------------
__global__ void cvt_split(const float* __restrict__ src,
                          __nv_bfloat16* __restrict__ dh,
                          __nv_bfloat16* __restrict__ dl, int n4)
{
    int i = blockIdx.x * blockDim.x + threadIdx.x;
    if (i >= n4) return;
    float4 x = *(const float4*)(src + (size_t)i * 4);
    __nv_bfloat16 h0 = __float2bfloat16(x.x), h1 = __float2bfloat16(x.y);
    __nv_bfloat16 h2 = __float2bfloat16(x.z), h3 = __float2bfloat16(x.w);
    __nv_bfloat16 l0 = __float2bfloat16(x.x - __bfloat162float(h0));
    __nv_bfloat16 l1 = __float2bfloat16(x.y - __bfloat162float(h1));
    __nv_bfloat16 l2 = __float2bfloat16(x.z - __bfloat162float(h2));
    __nv_bfloat16 l3 = __float2bfloat16(x.w - __bfloat162float(h3));
    __nv_bfloat162* ph = (__nv_bfloat162*)(dh + (size_t)i * 4);
    __nv_bfloat162* pl = (__nv_bfloat162*)(dl + (size_t)i * 4);
    ph[0] = __nv_bfloat162(h0, h1); ph[1] = __nv_bfloat162(h2, h3);
    pl[0] = __nv_bfloat162(l0, l1); pl[1] = __nv_bfloat162(l2, l3);
}

// ---------------------------------------------------------------------------
// Kernel 1: gi via mma.sync (HMMA) split-bf16, cp.async double-buffered.
// gi[m][n] = sum_k v[m][k] w[n][k] + b[n]  ~= Ah·Bh + Ah·Bl + Al·Bh (f32 acc).
// CTA 128x128 tile, 256 thr (8 warps x m16). K in 4 chunks of 64; chunk ch+1
// prefetched via cp.async into the alternate buffer while ch computes.
// Grid (nt=6 FASTEST, mt=512, dir=2): 6 consecutive CTAs share one A tile
// (L2 hit); B (1.5 MB) always L2-resident.
// SMEM: 2 buffers x (Ah|Al|Bh|Bl @ 128x144B) = 147456 B.
// ---------------------------------------------------------------------------
#define GM_MAT  18432               // one matrix: 128 rows x 144 B
#define GM_BUF  (4 * GM_MAT)        // 73728
#define GM_BYTES (2 * GM_BUF)       // 147456

__device__ __forceinline__ void gm_prefetch(
    uint32_t sbuf, const __nv_bfloat16* const (&srcs)[4], int ch, int tid)
{
#pragma unroll
    for (int it = 0; it < 16; ++it) {
        const int idx = tid + it * 256;
        const int m   = it >> 2;          // compile-time matrix select
        const int r   = (idx >> 3) & 127;
        const int c   = idx & 7;
        cp16(sbuf + m * GM_MAT + r * 144 + c * 16,
             srcs[m] + (size_t)r * 256 + ch * 64 + c * 8);
    }
    CP_COMMIT();
}

__global__ __launch_bounds__(256) void gi_mma(
    const float* __restrict__ bf, const float* __restrict__ bb)
{
    extern __shared__ __align__(16) char ms[];
    const int tid  = threadIdx.x;
    const int wid  = tid >> 5;
    const int lane = tid & 31;
    const int nbase = blockIdx.x * 128;   // nt fastest -> A-tile L2 reuse
    const int mbase = blockIdx.y * 128;
    const int dir   = blockIdx.z;
    const uint32_t sb = smem_u32(ms);

    const __nv_bfloat16* srcs[4] = {
        g_vh + (size_t)mbase * 256,
        g_vl + (size_t)mbase * 256,
        g_wh + ((size_t)dir * G3_ + nbase) * 256,
        g_wl + ((size_t)dir * G3_ + nbase) * 256
    };

    float acc[16][4];
#pragma unroll
    for (int t = 0; t < 16; t++)
#pragma unroll
        for (int q = 0; q < 4; q++) acc[t][q] = 0.f;

    // fragment sub-addresses (offsets within a buffer)
    const uint32_t a_off  = (uint32_t)((wid * 16 + (lane & 15)) * 144
                                       + (lane >> 4) * 16);
    const uint32_t b_row  = (uint32_t)((lane & 7) + ((lane >> 4) & 1) * 8);
    const uint32_t b_koff = (uint32_t)(((lane >> 3) & 1) * 16);

    gm_prefetch(sb, srcs, 0, tid);

    for (int ch = 0; ch < 4; ++ch) {
        const uint32_t buf = sb + (uint32_t)(ch & 1) * GM_BUF;
        if (ch < 3) {
            gm_prefetch(sb + (uint32_t)((ch + 1) & 1) * GM_BUF, srcs, ch + 1, tid);
            CP_WAIT(1);
        } else {
            CP_WAIT(0);
        }
        __syncthreads();

#pragma unroll
        for (int k16 = 0; k16 < 4; ++k16) {
            uint32_t ah[4], al[4];
            const uint32_t aa = buf + a_off + k16 * 32;
            LDSM4(ah, aa);
            LDSM4(al, aa + GM_MAT);

#pragma unroll
            for (int np = 0; np < 8; ++np) {
                const uint32_t ba = buf + 2 * GM_MAT + (np * 16 + b_row) * 144
                                    + b_koff + k16 * 32;
                uint32_t bh[4], bl[4];
                LDSM4(bh, ba);
                MMA16816(acc[2*np],   ah, (bh + 0));
                MMA16816(acc[2*np+1], ah, (bh + 2));
                MMA16816(acc[2*np],   al, (bh + 0));
                MMA16816(acc[2*np+1], al, (bh + 2));
                LDSM4(bl, ba + GM_MAT);
                MMA16816(acc[2*np],   ah, (bl + 0));
                MMA16816(acc[2*np+1], ah, (bl + 2));
            }
        }
        __syncthreads();
    }

    // ---- epilogue: D fragment (row = group, cols = thread*2) + bias
    const float* bih = dir ? bb : bf;
    float* gout = g_gi + ((size_t)dir * B_ * S_ + mbase) * G3_ + nbase;
    const int r0 = wid * 16 + (lane >> 2);
    const int cb = (lane & 3) * 2;
#pragma unroll
    for (int t = 0; t < 16; ++t) {
        const int col = t * 8 + cb;
        const float b0v = bih[nbase + col];
        const float b1v = bih[nbase + col + 1];
        float2 o0, o1;
        o0.x = acc[t][0] + b0v; o0.y = acc[t][1] + b1v;
        o1.x = acc[t][2] + b0v; o1.y = acc[t][3] + b1v;
        *(float2*)(gout + (size_t)r0 * G3_ + col)       = o0;
        *(float2*)(gout + (size_t)(r0 + 8) * G3_ + col) = o1;
    }
}

// ---------------------------------------------------------------------------
// Kernel 2: GRU recurrence — EXACT proven-best config (rec 3.15ms).
// Cluster of 4 CTAs = one (dir, batch-pair); 256 thr; jl=tid>>2, ks=tid&3;
// w_r,w_z register f32x2 pairs; w_n SMEM (stride-260); per-step
// __syncthreads + 4x mbarrier arrive.release.cluster + parity wait.
// ---------------------------------------------------------------------------
#define WN_STRIDE 260
#define SM_WN     0
#define SM_HBUF   (64 * WN_STRIDE)
#define SM_MBAR   (SM_HBUF + 1024)
#define SM_FLOATS (SM_MBAR + 4)
#define SM_BYTES  (SM_FLOATS * 4)

__global__ void __cluster_dims__(4, 1, 1) __launch_bounds__(256, 1)
rnn_rec(const float* __restrict__ whhf, const float* __restrict__ whhb,
        const float* __restrict__ bhhf, const float* __restrict__ bhhb,
        const float* __restrict__ V, float* __restrict__ out,
        int cl, int T)
{
    extern __shared__ __align__(16) float smem[];
    float* wn_s = smem + SM_WN;
    float* hbuf = smem + SM_HBUF;

    const int tid = threadIdx.x;
    const int jl  = tid >> 2;
    const int ks  = tid & 3;
    unsigned rank;
    asm("mov.u32 %0, %%cluster_ctarank;" : "=r"(rank));
    const int j   = (int)rank * 64 + jl;
    const int dir = blockIdx.z;
    const int b0  = blockIdx.y * 2;

    const float* __restrict__ WHH = dir ? whhb : whhf;
    const float* __restrict__ BHH = dir ? bhhb : bhhf;

    unsigned long long wr2[32], wz2[32];
    {
        const float* pr = WHH + (size_t)(      j) * 256 + ks * 64;
        const float* pz = WHH + (size_t)(256 + j) * 256 + ks * 64;
#pragma unroll
        for (int i = 0; i < 16; i++) {
            const int ci = (i ^ (ks << 1)) & 15;
            ulonglong2 q;
            q = *(const ulonglong2*)(pr + ci * 4);
            wr2[2*i] = q.x; wr2[2*i+1] = q.y;
            q = *(const ulonglong2*)(pz + ci * 4);
            wz2[2*i] = q.x; wz2[2*i+1] = q.y;
        }
    }
    const float br = BHH[j], bz = BHH[256 + j], bn = BHH[512 + j];

    {
        const float* srcn = WHH + (size_t)(512 + (int)rank * 64) * 256;
        for (int idx = tid; idx < 64 * 64; idx += 256) {
            const int u  = idx >> 6;
            const int c4 = idx & 63;
            *(float4*)(wn_s + u * WN_STRIDE + c4 * 4) =
                *(const float4*)(srcn + (size_t)u * 256 + c4 * 4);
        }
    }

    const uint32_t hb  = smem_u32(hbuf);
    const uint32_t mba = smem_u32(smem + SM_MBAR);

    if (tid < 128) ((float4*)hbuf)[tid] = make_float4(0.f, 0.f, 0.f, 0.f);
    if (tid == 0)
        asm volatile("mbarrier.init.shared.b64 [%0], %1;"
                     :: "r"(mba), "r"(4) : "memory");
    __syncthreads();
    asm volatile("barrier.cluster.arrive.aligned;" ::: "memory");
    asm volatile("barrier.cluster.wait.aligned;"   ::: "memory");

    const int s0 = dir ? (S_ - 1) : 0;
    const ptrdiff_t gstep = dir ? -(ptrdiff_t)G3_ : (ptrdiff_t)G3_;
    const ptrdiff_t vstep = dir ? -(ptrdiff_t)256 : (ptrdiff_t)256;
    const int bb = ks & 1;

    const float* gi_my = g_gi + ((size_t)dir * B_ + b0 + bb) * S_ * G3_
                              + (size_t)s0 * G3_ + j;
    const float* v_my  = V + ((size_t)(b0 + bb) * S_ + s0) * 256 + j;
    float* o_my        = out + (size_t)(b0 + bb) * T * 512 + (size_t)dir * 256 + j;

    const float* wn_row = wn_s + jl * WN_STRIDE + ks * 64;

    float g_r = 0.f, g_z = 0.f, g_n = 0.f, vv = 0.f, hp = 0.f;

    for (int step = 0; step < S_; ++step) {
        const int p = step & 1;
        const float* hs = hbuf + p * 512;

        if (ks < 2) {
            g_r = gi_my[0];
            g_z = gi_my[256];
            g_n = gi_my[512];
            vv  = v_my[0];
            hp  = hs[bb * 256 + j];
        }

        unsigned long long ar0 = 0, az0 = 0, an0 = 0;
        unsigned long long ar1 = 0, az1 = 0, an1 = 0;
        const float* h0 = hs + ks * 64;
        const float* h1 = hs + 256 + ks * 64;
#pragma unroll
        for (int i = 0; i < 16; i++) {
            const int ci = (i ^ (ks << 1)) & 15;
            ulonglong2 hv0 = *(const ulonglong2*)(h0 + 4 * ci);
            ulonglong2 hv1 = *(const ulonglong2*)(h1 + 4 * ci);
            ulonglong2 wn  = *(const ulonglong2*)(wn_row + 4 * ci);
            ffma2(ar0, wr2[2*i], hv0.x); ffma2(ar0, wr2[2*i+1], hv0.y);
            ffma2(az0, wz2[2*i], hv0.x); ffma2(az0, wz2[2*i+1], hv0.y);
            ffma2(an0, wn.x,     hv0.x); ffma2(an0, wn.y,       hv0.y);
            ffma2(ar1, wr2[2*i], hv1.x); ffma2(ar1, wr2[2*i+1], hv1.y);
            ffma2(az1, wz2[2*i], hv1.x); ffma2(az1, wz2[2*i+1], hv1.y);
            ffma2(an1, wn.x,     hv1.x); ffma2(an1, wn.y,       hv1.y);
        }

        float2 t;
        t = unpack2(ar0); float r0  = t.x + t.y;
        t = unpack2(az0); float z0  = t.x + t.y;
        t = unpack2(an0); float n0v = t.x + t.y;
        t = unpack2(ar1); float r1  = t.x + t.y;
        t = unpack2(az1); float z1  = t.x + t.y;
        t = unpack2(an1); float n1v = t.x + t.y;

        r0  += __shfl_xor_sync(0xffffffffu, r0, 1, 4);
        r0  += __shfl_xor_sync(0xffffffffu, r0, 2, 4);
        z0  += __shfl_xor_sync(0xffffffffu, z0, 1, 4);
        z0  += __shfl_xor_sync(0xffffffffu, z0, 2, 4);
        n0v += __shfl_xor_sync(0xffffffffu, n0v, 1, 4);
        n0v += __shfl_xor_sync(0xffffffffu, n0v, 2, 4);
        r1  += __shfl_xor_sync(0xffffffffu, r1, 1, 4);
        r1  += __shfl_xor_sync(0xffffffffu, r1, 2, 4);
        z1  += __shfl_xor_sync(0xffffffffu, z1, 1, 4);
        z1  += __shfl_xor_sync(0xffffffffu, z1, 2, 4);
        n1v += __shfl_xor_sync(0xffffffffu, n1v, 1, 4);
        n1v += __shfl_xor_sync(0xffffffffu, n1v, 2, 4);

        if (ks < 2) {
            const float ar = bb ? r1  : r0;
            const float az = bb ? z1  : z0;
            const float an = bb ? n1v : n0v;

            const float r  = fast_sig(g_r + ar + br);
            const float z  = fast_sig(g_z + az + bz);
            const float n  = fast_tanh(g_n + r * (an + bn));
            const float hn = (1.f - z) * n + z * hp;

            const uint32_t la = hb + 4u * (uint32_t)(((p ^ 1) * 2 + bb) * 256 + j);
#pragma unroll
            for (int rdst = 0; rdst < 4; rdst++) {
                uint32_t ra;
                asm("mapa.shared::cluster.u32 %0, %1, %2;"
                    : "=r"(ra) : "r"(la), "r"(rdst));
                asm volatile("st.shared::cluster.f32 [%0], %1;"
                             :: "r"(ra), "f"(hn) : "memory");
            }

            if ((unsigned)(step - cl) < (unsigned)T)
                o_my[(size_t)(step - cl) * 512] = hn + vv;
        }

        gi_my += gstep;
        v_my  += vstep;

        __syncthreads();
        if (tid < 4) {
            uint32_t ra;
            asm("mapa.shared::cluster.u32 %0, %1, %2;"
                : "=r"(ra) : "r"(mba), "r"(tid));
            asm volatile("mbarrier.arrive.release.cluster.shared::cluster.b64 _, [%0];"
                         :: "r"(ra) : "memory");
        }
        {
            const uint32_t par = (uint32_t)(step & 1);
            asm volatile(
                "{\n\t"
                ".reg .pred P;\n"
                "W%=:\n\t"
                "mbarrier.try_wait.parity.acquire.cluster.shared::cta.b64 P, [%0], %1, 0x989680;\n\t"
                "@!P bra W%=;\n\t"
                "}"
                :: "r"(mba), "r"(par) : "memory");
        }
    }
}

// ---------------------------------------------------------------------------
extern "C" void kernel_launch(void* const* d_in, const int* in_sizes, int n_in,
                              void* d_out, int out_size)
{
    const float* V    = (const float*)d_in[0];
    const float* wihf = (const float*)d_in[1];
    const float* whhf = (const float*)d_in[2];
    const float* bihf = (const float*)d_in[3];
    const float* bhhf = (const float*)d_in[4];
    const float* wihb = (const float*)d_in[5];
    const float* whhb = (const float*)d_in[6];
    const float* bihb = (const float*)d_in[7];
    const float* bhhb = (const float*)d_in[8];
    float* out = (float*)d_out;

    const int T  = out_size / (B_ * 512);   // 2028
    const int cl = (S_ - T) / 2;            // 10

    __nv_bfloat16 *vh, *vl, *wh, *wl;
    cudaGetSymbolAddress((void**)&vh, g_vh);
    cudaGetSymbolAddress((void**)&vl, g_vl);
    cudaGetSymbolAddress((void**)&wh, g_wh);
    cudaGetSymbolAddress((void**)&wl, g_wl);

    // split fp32 -> bf16 hi/lo
    cvt_split<<<(B_ * S_ * D_) / 1024, 256>>>(V, vh, vl, (B_ * S_ * D_) / 4);
    cvt_split<<<(G3_ * D_) / 1024, 256>>>(wihf, wh, wl, (G3_ * D_) / 4);
    cvt_split<<<(G3_ * D_) / 1024, 256>>>(wihb, wh + (size_t)G3_ * D_,
                                          wl + (size_t)G3_ * D_, (G3_ * D_) / 4);

    // tensor-core (HMMA) gi GEMM, cp.async double-buffered
    cudaFuncSetAttribute(gi_mma, cudaFuncAttributeMaxDynamicSharedMemorySize,
                         GM_BYTES);
    gi_mma<<<dim3(G3_ / 128, (B_ * S_) / 128, 2), 256, GM_BYTES>>>(bihf, bihb);

    // recurrence (proven-best config, frozen)
    cudaFuncSetAttribute(rnn_rec, cudaFuncAttributeMaxDynamicSharedMemorySize,
                         SM_BYTES);
    rnn_rec<<<dim3(4, B_ / 2, 2), 256, SM_BYTES>>>(whhf, whhb, bhhf, bhhb,
                                                   V, out, cl, T);
}

// round 17
// speedup vs baseline: 2.0758x; 1.0028x over previous
#include <cuda_runtime.h>
#include <cuda_bf16.h>
#include <cstdint>
#include <cstddef>

#define B_   32
#define S_   2048
#define D_   256
#define G3_  768

// scratch: gi [dir][b][s][768], split-bf16 copies of v and w_ih
__device__ float          g_gi[(size_t)2 * B_ * S_ * G3_];
__device__ __nv_bfloat16  g_vh[(size_t)B_ * S_ * D_];
__device__ __nv_bfloat16  g_vl[(size_t)B_ * S_ * D_];
__device__ __nv_bfloat16  g_wh[(size_t)2 * G3_ * D_];
__device__ __nv_bfloat16  g_wl[(size_t)2 * G3_ * D_];

// ---------------------------------------------------------------------------
// helpers
// ---------------------------------------------------------------------------
__device__ __forceinline__ float2 unpack2(unsigned long long v) {
    float2 f;
    asm("mov.b64 {%0,%1}, %2;" : "=f"(f.x), "=f"(f.y) : "l"(v));
    return f;
}
__device__ __forceinline__ void ffma2(unsigned long long& d,
                                      unsigned long long a,
                                      unsigned long long b) {
    asm("fma.rn.f32x2 %0, %1, %2, %0;" : "+l"(d) : "l"(a), "l"(b));
}
__device__ __forceinline__ uint32_t smem_u32(const void* p) {
    uint32_t a;
    asm("{ .reg .u64 t; cvta.to.shared.u64 t, %1; cvt.u32.u64 %0, t; }"
        : "=r"(a) : "l"(p));
    return a;
}
__device__ __forceinline__ float fast_sig(float x) {
    return __fdividef(1.f, 1.f + __expf(-x));
}
__device__ __forceinline__ float fast_tanh(float x) {
    return __fdividef(2.f, 1.f + __expf(-2.f * x)) - 1.f;
}
__device__ __forceinline__ void cp16(uint32_t s, const void* g) {
    asm volatile("cp.async.cg.shared.global [%0], [%1], 16;"
                 :: "r"(s), "l"(g) : "memory");
}
#define CP_COMMIT() asm volatile("cp.async.commit_group;" ::: "memory")
#define CP_WAIT(n)  asm volatile("cp.async.wait_group %0;" :: "n"(n) : "memory")

#define LDSM4(r, a)                                                           \
    asm volatile("ldmatrix.sync.aligned.m8n8.x4.shared.b16 {%0,%1,%2,%3}, [%4];" \
                 : "=r"((r)[0]), "=r"((r)[1]), "=r"((r)[2]), "=r"((r)[3])     \
                 : "r"(a))

#define MMA16816(d, a, b)                                                     \
    asm volatile("mma.sync.aligned.m16n8k16.row.col.f32.bf16.bf16.f32 "       \
                 "{%0,%1,%2,%3}, {%4,%5,%6,%7}, {%8,%9}, {%0,%1,%2,%3};"      \
                 : "+f"((d)[0]), "+f"((d)[1]), "+f"((d)[2]), "+f"((d)[3])     \
                 : "r"((a)[0]), "r"((a)[1]), "r"((a)[2]), "r"((a)[3]),        \
                   "r"((b)[0]), "r"((b)[1]))

// ---------------------------------------------------------------------------
// Kernel 0: split fp32 -> bf16 hi + bf16 lo (residual)
// ---------------------------------------------------------------------------
__global__ void cvt_split(const float* __restrict__ src,
                          __nv_bfloat16* __restrict__ dh,
                          __nv_bfloat16* __restrict__ dl, int n4)
{
    int i = blockIdx.x * blockDim.x + threadIdx.x;
    if (i >= n4) return;
    float4 x = *(const float4*)(src + (size_t)i * 4);
    __nv_bfloat16 h0 = __float2bfloat16(x.x), h1 = __float2bfloat16(x.y);
    __nv_bfloat16 h2 = __float2bfloat16(x.z), h3 = __float2bfloat16(x.w);
    __nv_bfloat16 l0 = __float2bfloat16(x.x - __bfloat162float(h0));
    __nv_bfloat16 l1 = __float2bfloat16(x.y - __bfloat162float(h1));
    __nv_bfloat16 l2 = __float2bfloat16(x.z - __bfloat162float(h2));
    __nv_bfloat16 l3 = __float2bfloat16(x.w - __bfloat162float(h3));
    __nv_bfloat162* ph = (__nv_bfloat162*)(dh + (size_t)i * 4);
    __nv_bfloat162* pl = (__nv_bfloat162*)(dl + (size_t)i * 4);
    ph[0] = __nv_bfloat162(h0, h1); ph[1] = __nv_bfloat162(h2, h3);
    pl[0] = __nv_bfloat162(l0, l1); pl[1] = __nv_bfloat162(l2, l3);
}

// ---------------------------------------------------------------------------
// Kernel 1: gi via mma.sync (HMMA) split-bf16, cp.async double-buffered,
// register-pipelined B fragments (prefetch np+1 while MMA np).
// gi[m][n] = sum_k v[m][k] w[n][k] + b[n]  ~= Ah·Bh + Ah·Bl + Al·Bh (f32 acc).
// CTA 128x128 tile, 256 thr (8 warps x m16). K in 4 chunks of 64.
// Grid (nt=6 FASTEST, mt=512, dir=2): 6 consecutive CTAs share one A tile.
// SMEM: 2 buffers x (Ah|Al|Bh|Bl @ 128x144B) = 147456 B.
// ---------------------------------------------------------------------------
#define GM_MAT  18432               // one matrix: 128 rows x 144 B
#define GM_BUF  (4 * GM_MAT)        // 73728
#define GM_BYTES (2 * GM_BUF)       // 147456

__device__ __forceinline__ void gm_prefetch(
    uint32_t sbuf, const __nv_bfloat16* const (&srcs)[4], int ch, int tid)
{
#pragma unroll
    for (int it = 0; it < 16; ++it) {
        const int idx = tid + it * 256;
        const int m   = it >> 2;          // compile-time matrix select
        const int r   = (idx >> 3) & 127;
        const int c   = idx & 7;
        cp16(sbuf + m * GM_MAT + r * 144 + c * 16,
             srcs[m] + (size_t)r * 256 + ch * 64 + c * 8);
    }
    CP_COMMIT();
}

__global__ __launch_bounds__(256) void gi_mma(
    const float* __restrict__ bf, const float* __restrict__ bb)
{
    extern __shared__ __align__(16) char ms[];
    const int tid  = threadIdx.x;
    const int wid  = tid >> 5;
    const int lane = tid & 31;
    const int nbase = blockIdx.x * 128;   // nt fastest -> A-tile L2 reuse
    const int mbase = blockIdx.y * 128;
    const int dir   = blockIdx.z;
    const uint32_t sb = smem_u32(ms);

    const __nv_bfloat16* srcs[4] = {
        g_vh + (size_t)mbase * 256,
        g_vl + (size_t)mbase * 256,
        g_wh + ((size_t)dir * G3_ + nbase) * 256,
        g_wl + ((size_t)dir * G3_ + nbase) * 256
    };

    float acc[16][4];
#pragma unroll
    for (int t = 0; t < 16; t++)
#pragma unroll
        for (int q = 0; q < 4; q++) acc[t][q] = 0.f;

    // fragment sub-addresses (offsets within a buffer)
    const uint32_t a_off  = (uint32_t)((wid * 16 + (lane & 15)) * 144
                                       + (lane >> 4) * 16);
    const uint32_t b_off  = (uint32_t)(((lane & 7) + ((lane >> 4) & 1) * 8) * 144
                                       + ((lane >> 3) & 1) * 16);

    gm_prefetch(sb, srcs, 0, tid);

    for (int ch = 0; ch < 4; ++ch) {
        const uint32_t buf = sb + (uint32_t)(ch & 1) * GM_BUF;
        if (ch < 3) {
            gm_prefetch(sb + (uint32_t)((ch + 1) & 1) * GM_BUF, srcs, ch + 1, tid);
            CP_WAIT(1);
        } else {
            CP_WAIT(0);
        }
        __syncthreads();

#pragma unroll
        for (int k16 = 0; k16 < 4; ++k16) {
            uint32_t ah[4], al[4];
            const uint32_t aa = buf + a_off + k16 * 32;
            LDSM4(ah, aa);
            LDSM4(al, aa + GM_MAT);

            // B-fragment register double-buffer: prefetch np+1 before MMA np
            uint32_t bh[2][4], bl[2][4];
            const uint32_t bb0 = buf + 2 * GM_MAT + b_off + k16 * 32;
            LDSM4(bh[0], bb0);
            LDSM4(bl[0], bb0 + GM_MAT);

#pragma unroll
            for (int np = 0; np < 8; ++np) {
                const int cur = np & 1;
                const int nxt = cur ^ 1;
                if (np < 7) {
                    const uint32_t ba = bb0 + (uint32_t)(np + 1) * (16 * 144);
                    LDSM4(bh[nxt], ba);
                    LDSM4(bl[nxt], ba + GM_MAT);
                }
                MMA16816(acc[2*np],   ah, (bh[cur] + 0));
                MMA16816(acc[2*np+1], ah, (bh[cur] + 2));
                MMA16816(acc[2*np],   al, (bh[cur] + 0));
                MMA16816(acc[2*np+1], al, (bh[cur] + 2));
                MMA16816(acc[2*np],   ah, (bl[cur] + 0));
                MMA16816(acc[2*np+1], ah, (bl[cur] + 2));
            }
        }
        __syncthreads();
    }

    // ---- epilogue: D fragment (row = group, cols = thread*2) + bias
    const float* bih = dir ? bb : bf;
    float* gout = g_gi + ((size_t)dir * B_ * S_ + mbase) * G3_ + nbase;
    const int r0 = wid * 16 + (lane >> 2);
    const int cb = (lane & 3) * 2;
#pragma unroll
    for (int t = 0; t < 16; ++t) {
        const int col = t * 8 + cb;
        const float b0v = bih[nbase + col];
        const float b1v = bih[nbase + col + 1];
        float2 o0, o1;
        o0.x = acc[t][0] + b0v; o0.y = acc[t][1] + b1v;
        o1.x = acc[t][2] + b0v; o1.y = acc[t][3] + b1v;
        *(float2*)(gout + (size_t)r0 * G3_ + col)       = o0;
        *(float2*)(gout + (size_t)(r0 + 8) * G3_ + col) = o1;
    }
}

// ---------------------------------------------------------------------------
// Kernel 2: GRU recurrence — EXACT proven-best config (rec 3.15ms), frozen.
// Cluster of 4 CTAs = one (dir, batch-pair); 256 thr; jl=tid>>2, ks=tid&3;
// w_r,w_z register f32x2 pairs; w_n SMEM (stride-260); per-step
// __syncthreads + 4x mbarrier arrive.release.cluster + parity wait.
// ---------------------------------------------------------------------------
#define WN_STRIDE 260
#define SM_WN     0
#define SM_HBUF   (64 * WN_STRIDE)
#define SM_MBAR   (SM_HBUF + 1024)
#define SM_FLOATS (SM_MBAR + 4)
#define SM_BYTES  (SM_FLOATS * 4)

__global__ void __cluster_dims__(4, 1, 1) __launch_bounds__(256, 1)
rnn_rec(const float* __restrict__ whhf, const float* __restrict__ whhb,
        const float* __restrict__ bhhf, const float* __restrict__ bhhb,
        const float* __restrict__ V, float* __restrict__ out,
        int cl, int T)
{
    extern __shared__ __align__(16) float smem[];
    float* wn_s = smem + SM_WN;
    float* hbuf = smem + SM_HBUF;

    const int tid = threadIdx.x;
    const int jl  = tid >> 2;
    const int ks  = tid & 3;
    unsigned rank;
    asm("mov.u32 %0, %%cluster_ctarank;" : "=r"(rank));
    const int j   = (int)rank * 64 + jl;
    const int dir = blockIdx.z;
    const int b0  = blockIdx.y * 2;

    const float* __restrict__ WHH = dir ? whhb : whhf;
    const float* __restrict__ BHH = dir ? bhhb : bhhf;

    unsigned long long wr2[32], wz2[32];
    {
        const float* pr = WHH + (size_t)(      j) * 256 + ks * 64;
        const float* pz = WHH + (size_t)(256 + j) * 256 + ks * 64;
#pragma unroll
        for (int i = 0; i < 16; i++) {
            const int ci = (i ^ (ks << 1)) & 15;
            ulonglong2 q;
            q = *(const ulonglong2*)(pr + ci * 4);
            wr2[2*i] = q.x; wr2[2*i+1] = q.y;
            q = *(const ulonglong2*)(pz + ci * 4);
            wz2[2*i] = q.x; wz2[2*i+1] = q.y;
        }
    }
    const float br = BHH[j], bz = BHH[256 + j], bn = BHH[512 + j];

    {
        const float* srcn = WHH + (size_t)(512 + (int)rank * 64) * 256;
        for (int idx = tid; idx < 64 * 64; idx += 256) {
            const int u  = idx >> 6;
            const int c4 = idx & 63;
            *(float4*)(wn_s + u * WN_STRIDE + c4 * 4) =
                *(const float4*)(srcn + (size_t)u * 256 + c4 * 4);
        }
    }

    const uint32_t hb  = smem_u32(hbuf);
    const uint32_t mba = smem_u32(smem + SM_MBAR);

    if (tid < 128) ((float4*)hbuf)[tid] = make_float4(0.f, 0.f, 0.f, 0.f);
    if (tid == 0)
        asm volatile("mbarrier.init.shared.b64 [%0], %1;"
                     :: "r"(mba), "r"(4) : "memory");
    __syncthreads();
    asm volatile("barrier.cluster.arrive.aligned;" ::: "memory");
    asm volatile("barrier.cluster.wait.aligned;"   ::: "memory");

    const int s0 = dir ? (S_ - 1) : 0;
    const ptrdiff_t gstep = dir ? -(ptrdiff_t)G3_ : (ptrdiff_t)G3_;
    const ptrdiff_t vstep = dir ? -(ptrdiff_t)256 : (ptrdiff_t)256;
    const int bb2 = ks & 1;

    const float* gi_my = g_gi + ((size_t)dir * B_ + b0 + bb2) * S_ * G3_
                              + (size_t)s0 * G3_ + j;
    const float* v_my  = V + ((size_t)(b0 + bb2) * S_ + s0) * 256 + j;
    float* o_my        = out + (size_t)(b0 + bb2) * T * 512 + (size_t)dir * 256 + j;

    const float* wn_row = wn_s + jl * WN_STRIDE + ks * 64;

    float g_r = 0.f, g_z = 0.f, g_n = 0.f, vv = 0.f, hp = 0.f;

    for (int step = 0; step < S_; ++step) {
        const int p = step & 1;
        const float* hs = hbuf + p * 512;

        if (ks < 2) {
            g_r = gi_my[0];
            g_z = gi_my[256];
            g_n = gi_my[512];
            vv  = v_my[0];
            hp  = hs[bb2 * 256 + j];
        }

        unsigned long long ar0 = 0, az0 = 0, an0 = 0;
        unsigned long long ar1 = 0, az1 = 0, an1 = 0;
        const float* h0 = hs + ks * 64;
        const float* h1 = hs + 256 + ks * 64;
#pragma unroll
        for (int i = 0; i < 16; i++) {
            const int ci = (i ^ (ks << 1)) & 15;
            ulonglong2 hv0 = *(const ulonglong2*)(h0 + 4 * ci);
            ulonglong2 hv1 = *(const ulonglong2*)(h1 + 4 * ci);
            ulonglong2 wn  = *(const ulonglong2*)(wn_row + 4 * ci);
            ffma2(ar0, wr2[2*i], hv0.x); ffma2(ar0, wr2[2*i+1], hv0.y);
            ffma2(az0, wz2[2*i], hv0.x); ffma2(az0, wz2[2*i+1], hv0.y);
            ffma2(an0, wn.x,     hv0.x); ffma2(an0, wn.y,       hv0.y);
            ffma2(ar1, wr2[2*i], hv1.x); ffma2(ar1, wr2[2*i+1], hv1.y);
            ffma2(az1, wz2[2*i], hv1.x); ffma2(az1, wz2[2*i+1], hv1.y);
            ffma2(an1, wn.x,     hv1.x); ffma2(an1, wn.y,       hv1.y);
        }

        float2 t;
        t = unpack2(ar0); float r0  = t.x + t.y;
        t = unpack2(az0); float z0  = t.x + t.y;
        t = unpack2(an0); float n0v = t.x + t.y;
        t = unpack2(ar1); float r1  = t.x + t.y;
        t = unpack2(az1); float z1  = t.x + t.y;
        t = unpack2(an1); float n1v = t.x + t.y;

        r0  += __shfl_xor_sync(0xffffffffu, r0, 1, 4);
        r0  += __shfl_xor_sync(0xffffffffu, r0, 2, 4);
        z0  += __shfl_xor_sync(0xffffffffu, z0, 1, 4);
        z0  += __shfl_xor_sync(0xffffffffu, z0, 2, 4);
        n0v += __shfl_xor_sync(0xffffffffu, n0v, 1, 4);
        n0v += __shfl_xor_sync(0xffffffffu, n0v, 2, 4);
        r1  += __shfl_xor_sync(0xffffffffu, r1, 1, 4);
        r1  += __shfl_xor_sync(0xffffffffu, r1, 2, 4);
        z1  += __shfl_xor_sync(0xffffffffu, z1, 1, 4);
        z1  += __shfl_xor_sync(0xffffffffu, z1, 2, 4);
        n1v += __shfl_xor_sync(0xffffffffu, n1v, 1, 4);
        n1v += __shfl_xor_sync(0xffffffffu, n1v, 2, 4);

        if (ks < 2) {
            const float ar = bb2 ? r1  : r0;
            const float az = bb2 ? z1  : z0;
            const float an = bb2 ? n1v : n0v;

            const float r  = fast_sig(g_r + ar + br);
            const float z  = fast_sig(g_z + az + bz);
            const float n  = fast_tanh(g_n + r * (an + bn));
            const float hn = (1.f - z) * n + z * hp;

            const uint32_t la = hb + 4u * (uint32_t)(((p ^ 1) * 2 + bb2) * 256 + j);
#pragma unroll
            for (int rdst = 0; rdst < 4; rdst++) {
                uint32_t ra;
                asm("mapa.shared::cluster.u32 %0, %1, %2;"
                    : "=r"(ra) : "r"(la), "r"(rdst));
                asm volatile("st.shared::cluster.f32 [%0], %1;"
                             :: "r"(ra), "f"(hn) : "memory");
            }

            if ((unsigned)(step - cl) < (unsigned)T)
                o_my[(size_t)(step - cl) * 512] = hn + vv;
        }

        gi_my += gstep;
        v_my  += vstep;

        __syncthreads();
        if (tid < 4) {
            uint32_t ra;
            asm("mapa.shared::cluster.u32 %0, %1, %2;"
                : "=r"(ra) : "r"(mba), "r"(tid));
            asm volatile("mbarrier.arrive.release.cluster.shared::cluster.b64 _, [%0];"
                         :: "r"(ra) : "memory");
        }
        {
            const uint32_t par = (uint32_t)(step & 1);
            asm volatile(
                "{\n\t"
                ".reg .pred P;\n"
                "W%=:\n\t"
                "mbarrier.try_wait.parity.acquire.cluster.shared::cta.b64 P, [%0], %1, 0x989680;\n\t"
                "@!P bra W%=;\n\t"
                "}"
                :: "r"(mba), "r"(par) : "memory");
        }
    }
}

// ---------------------------------------------------------------------------
extern "C" void kernel_launch(void* const* d_in, const int* in_sizes, int n_in,
                              void* d_out, int out_size)
{
    const float* V    = (const float*)d_in[0];
    const float* wihf = (const float*)d_in[1];
    const float* whhf = (const float*)d_in[2];
    const float* bihf = (const float*)d_in[3];
    const float* bhhf = (const float*)d_in[4];
    const float* wihb = (const float*)d_in[5];
    const float* whhb = (const float*)d_in[6];
    const float* bihb = (const float*)d_in[7];
    const float* bhhb = (const float*)d_in[8];
    float* out = (float*)d_out;

    const int T  = out_size / (B_ * 512);   // 2028
    const int cl = (S_ - T) / 2;            // 10

    __nv_bfloat16 *vh, *vl, *wh, *wl;
    cudaGetSymbolAddress((void**)&vh, g_vh);
    cudaGetSymbolAddress((void**)&vl, g_vl);
    cudaGetSymbolAddress((void**)&wh, g_wh);
    cudaGetSymbolAddress((void**)&wl, g_wl);

    // split fp32 -> bf16 hi/lo
    cvt_split<<<(B_ * S_ * D_) / 1024, 256>>>(V, vh, vl, (B_ * S_ * D_) / 4);
    cvt_split<<<(G3_ * D_) / 1024, 256>>>(wihf, wh, wl, (G3_ * D_) / 4);
    cvt_split<<<(G3_ * D_) / 1024, 256>>>(wihb, wh + (size_t)G3_ * D_,
                                          wl + (size_t)G3_ * D_, (G3_ * D_) / 4);

    // tensor-core (HMMA) gi GEMM, cp.async + register pipelined
    cudaFuncSetAttribute(gi_mma, cudaFuncAttributeMaxDynamicSharedMemorySize,
                         GM_BYTES);
    gi_mma<<<dim3(G3_ / 128, (B_ * S_) / 128, 2), 256, GM_BYTES>>>(bihf, bihb);

    // recurrence (proven-best config, frozen)
    cudaFuncSetAttribute(rnn_rec, cudaFuncAttributeMaxDynamicSharedMemorySize,
                         SM_BYTES);
    rnn_rec<<<dim3(4, B_ / 2, 2), 256, SM_BYTES>>>(whhf, whhb, bhhf, bhhb,
                                                   V, out, cl, T);
}